// round 1
// baseline (speedup 1.0000x reference)
#include <cuda_runtime.h>
#include <cstdint>
#include <cstddef>

#define NND 50000
#define NE  500000
#define HD  128
#define NHD 8

// ---------------- scratch (device globals: allocation-free) ----------------
__device__ float    g_agg[NND * HD];
__device__ float    g_t1 [NND * HD];
__device__ float    g_xl [NND * HD];
__device__ float    g_q  [NND * HD];
__device__ float    g_k  [NND * HD];
__device__ float    g_v  [NND * HD];
__device__ float    g_xa [NND * HD];
__device__ float    g_hc [NND * HD];
__device__ float    g_xo [NND * HD];
__device__ float    g_ffn[NND * 2 * HD];
__device__ float    g_s  [NE * NHD];
__device__ unsigned g_mx [NND * NHD];
__device__ float    g_den[NND * NHD];
__device__ float    g_sum[3 * HD];
__device__ float    g_ssq[3 * HD];

// ---------------- helpers ----------------
__device__ __forceinline__ unsigned fenc(float f) {
    unsigned u = __float_as_uint(f);
    return (u & 0x80000000u) ? ~u : (u | 0x80000000u);
}
__device__ __forceinline__ float fdec(unsigned u) {
    return __uint_as_float((u & 0x80000000u) ? (u & 0x7fffffffu) : ~u);
}
__device__ __forceinline__ void red4(float* p, float4 v) {
    asm volatile("red.global.add.v4.f32 [%0], {%1,%2,%3,%4};"
                 :: "l"(p), "f"(v.x), "f"(v.y), "f"(v.z), "f"(v.w) : "memory");
}

// ---------------- zero scratch ----------------
__global__ void zero_kernel() {
    int i = blockIdx.x * blockDim.x + threadIdx.x;
    if (i < NND * HD) { g_agg[i] = 0.f; g_xa[i] = 0.f; }
    if (i < NND * NHD) { g_den[i] = 0.f; g_mx[i] = 0u; }
    if (i < 3 * HD)   { g_sum[i] = 0.f; g_ssq[i] = 0.f; }
}

// ---------------- GINE message: agg[dst] += relu(h[src] + eattr) ; 1 warp/edge ----------------
__global__ void msg_kernel(const float* __restrict__ h, const float* __restrict__ eattr,
                           const int* __restrict__ src, const int* __restrict__ dst) {
    int gid  = blockIdx.x * blockDim.x + threadIdx.x;
    int e    = gid >> 5;
    int lane = gid & 31;
    if (e >= NE) return;
    int sr = src[e], ds = dst[e];
    const float4 hv = *(const float4*)(h + (size_t)sr * HD + lane * 4);
    const float4 ev = *(const float4*)(eattr + (size_t)e * HD + lane * 4);
    float4 m;
    m.x = fmaxf(hv.x + ev.x, 0.f);
    m.y = fmaxf(hv.y + ev.y, 0.f);
    m.z = fmaxf(hv.z + ev.z, 0.f);
    m.w = fmaxf(hv.w + ev.w, 0.f);
    red4(&g_agg[(size_t)ds * HD + lane * 4], m);
}

// ---------------- fp32 tiled GEMM:  C = epi( (A(+A2)) @ W^T + bias )  ----------------
// A:[M,K] row-major (optionally + A2), W:[Nn,K] row-major, C:[M,Nn]
// epi: v=(acc+bias[c])*scale ; relu? ; +addend[r,c]?
__global__ __launch_bounds__(256)
void sgemm_kernel(const float* __restrict__ A, const float* __restrict__ A2,
                  const float* __restrict__ W, const float* __restrict__ bias,
                  const float* __restrict__ addend, float* __restrict__ C,
                  int M, int Nn, int K, int doRelu, float scale) {
    __shared__ float As[16][128];
    __shared__ float Ws[16][128];
    const int tid = threadIdx.x;
    const int tx = tid & 15;        // 16 col-groups of 8
    const int ty = tid >> 4;        // 16 row-groups of 8
    const int row0 = blockIdx.y * 128;
    const int col0 = blockIdx.x * 128;

    float acc[8][8];
#pragma unroll
    for (int i = 0; i < 8; i++)
#pragma unroll
        for (int j = 0; j < 8; j++) acc[i][j] = 0.f;

    for (int kt = 0; kt < K; kt += 16) {
#pragma unroll
        for (int l = 0; l < 2; l++) {
            int linear = tid + l * 256;      // 0..511
            int r  = linear >> 2;            // 0..127
            int c4 = (linear & 3) << 2;      // 0,4,8,12
            int gr = row0 + r;
            float4 av = make_float4(0.f, 0.f, 0.f, 0.f);
            if (gr < M) {
                av = *(const float4*)(A + (size_t)gr * K + kt + c4);
                if (A2) {
                    float4 bv = *(const float4*)(A2 + (size_t)gr * K + kt + c4);
                    av.x += bv.x; av.y += bv.y; av.z += bv.z; av.w += bv.w;
                }
            }
            As[c4 + 0][r] = av.x; As[c4 + 1][r] = av.y;
            As[c4 + 2][r] = av.z; As[c4 + 3][r] = av.w;
            float4 wv = *(const float4*)(W + (size_t)(col0 + r) * K + kt + c4);
            Ws[c4 + 0][r] = wv.x; Ws[c4 + 1][r] = wv.y;
            Ws[c4 + 2][r] = wv.z; Ws[c4 + 3][r] = wv.w;
        }
        __syncthreads();
#pragma unroll
        for (int k = 0; k < 16; k++) {
            float4 a0 = *(const float4*)&As[k][ty * 8];
            float4 a1 = *(const float4*)&As[k][ty * 8 + 4];
            float4 b0 = *(const float4*)&Ws[k][tx * 8];
            float4 b1 = *(const float4*)&Ws[k][tx * 8 + 4];
            float ra[8] = {a0.x, a0.y, a0.z, a0.w, a1.x, a1.y, a1.z, a1.w};
            float rb[8] = {b0.x, b0.y, b0.z, b0.w, b1.x, b1.y, b1.z, b1.w};
#pragma unroll
            for (int i = 0; i < 8; i++)
#pragma unroll
                for (int j = 0; j < 8; j++) acc[i][j] += ra[i] * rb[j];
        }
        __syncthreads();
    }

#pragma unroll
    for (int i = 0; i < 8; i++) {
        int r = row0 + ty * 8 + i;
        if (r >= M) continue;
#pragma unroll
        for (int j0 = 0; j0 < 8; j0 += 4) {
            int c = col0 + tx * 8 + j0;
            float4 o;
            o.x = (acc[i][j0 + 0] + bias[c + 0]) * scale;
            o.y = (acc[i][j0 + 1] + bias[c + 1]) * scale;
            o.z = (acc[i][j0 + 2] + bias[c + 2]) * scale;
            o.w = (acc[i][j0 + 3] + bias[c + 3]) * scale;
            if (doRelu) {
                o.x = fmaxf(o.x, 0.f); o.y = fmaxf(o.y, 0.f);
                o.z = fmaxf(o.z, 0.f); o.w = fmaxf(o.w, 0.f);
            }
            if (addend) {
                float4 ad = *(const float4*)(addend + (size_t)r * Nn + c);
                o.x += ad.x; o.y += ad.y; o.z += ad.z; o.w += ad.w;
            }
            *(float4*)(C + (size_t)r * Nn + c) = o;
        }
    }
}

// ---------------- per-edge attention scores + segment max ----------------
__global__ void score_kernel(const int* __restrict__ src, const int* __restrict__ dst) {
    int i = blockIdx.x * blockDim.x + threadIdx.x;
    if (i >= NE * NHD) return;
    int e = i >> 3, hd = i & 7;
    int sr = src[e], ds = dst[e];
    const float4* qp = (const float4*)(g_q + (size_t)sr * HD + hd * 16);
    const float4* kp = (const float4*)(g_k + (size_t)ds * HD + hd * 16);
    float acc = 0.f;
#pragma unroll
    for (int j = 0; j < 4; j++) {
        float4 a = qp[j], b = kp[j];
        acc += a.x * b.x + a.y * b.y + a.z * b.z + a.w * b.w;
    }
    g_s[i] = acc;
    atomicMax(&g_mx[sr * NHD + hd], fenc(acc));
}

// ---------------- p = exp(s - m[src]) ; denom[src] += p ----------------
__global__ void psum_kernel(const int* __restrict__ src) {
    int i = blockIdx.x * blockDim.x + threadIdx.x;
    if (i >= NE * NHD) return;
    int e = i >> 3, hd = i & 7;
    int sr = src[e];
    float mm = fdec(g_mx[sr * NHD + hd]);
    float p = expf(g_s[i] - mm);
    g_s[i] = p;
    atomicAdd(&g_den[sr * NHD + hd], p);
}

// ---------------- out[src] += (p/denom[src]) * v[dst] ; 1 warp/edge ----------------
__global__ void avout_kernel(const int* __restrict__ src, const int* __restrict__ dst) {
    int gid  = blockIdx.x * blockDim.x + threadIdx.x;
    int e    = gid >> 5;
    int lane = gid & 31;
    if (e >= NE) return;
    int sr = src[e], ds = dst[e];
    int hd = lane >> 2;
    float attn = g_s[(size_t)e * NHD + hd] / g_den[sr * NHD + hd];
    float4 vv = *(const float4*)(g_v + (size_t)ds * HD + lane * 4);
    vv.x *= attn; vv.y *= attn; vv.z *= attn; vv.w *= attn;
    red4(&g_xa[(size_t)sr * HD + lane * 4], vv);
}

// ---------------- BN statistics (optionally x += add first) ----------------
__global__ void stats_kernel(float* __restrict__ x, const float* __restrict__ add, int slot) {
    int c  = threadIdx.x;             // 128 channels
    int r0 = blockIdx.x * 64;
    float s = 0.f, ss = 0.f;
    for (int i = 0; i < 64; i++) {
        int r = r0 + i;
        if (r < NND) {
            size_t idx = (size_t)r * HD + c;
            float v = x[idx];
            if (add) { v += add[idx]; x[idx] = v; }
            s += v; ss += v * v;
        }
    }
    atomicAdd(&g_sum[slot * HD + c], s);
    atomicAdd(&g_ssq[slot * HD + c], ss);
}

// ---------------- hc = bn0(xl) + bn1(xa) ----------------
__global__ void combine_kernel(const float* __restrict__ nl_g, const float* __restrict__ nl_b,
                               const float* __restrict__ na_g, const float* __restrict__ na_b) {
    int i = blockIdx.x * blockDim.x + threadIdx.x;
    if (i >= NND * HD) return;
    int c = i & (HD - 1);
    const float invN = 1.f / (float)NND;
    float mu0 = g_sum[c] * invN;
    float v0  = g_ssq[c] * invN - mu0 * mu0;
    float i0  = rsqrtf(v0 + 1e-5f);
    float mu1 = g_sum[HD + c] * invN;
    float v1  = g_ssq[HD + c] * invN - mu1 * mu1;
    float i1  = rsqrtf(v1 + 1e-5f);
    float a = (g_xl[i] - mu0) * i0 * nl_g[c] + nl_b[c];
    float b = (g_xa[i] - mu1) * i1 * na_g[c] + na_b[c];
    g_hc[i] = a + b;
}

// ---------------- out = bn2(xo) ----------------
__global__ void apply_kernel(const float* __restrict__ no_g, const float* __restrict__ no_b,
                             float* __restrict__ out) {
    int i = blockIdx.x * blockDim.x + threadIdx.x;
    if (i >= NND * HD) return;
    int c = i & (HD - 1);
    const float invN = 1.f / (float)NND;
    float mu = g_sum[2 * HD + c] * invN;
    float v  = g_ssq[2 * HD + c] * invN - mu * mu;
    float iv = rsqrtf(v + 1e-5f);
    out[i] = (g_xo[i] - mu) * iv * no_g[c] + no_b[c];
}

// ---------------- host launcher ----------------
extern "C" void kernel_launch(void* const* d_in, const int* in_sizes, int n_in,
                              void* d_out, int out_size) {
    const float* h      = (const float*)d_in[0];
    const float* eattr  = (const float*)d_in[1];
    const int*   src    = (const int*)  d_in[2];
    const int*   dst    = (const int*)  d_in[3];
    const float* gin_w1 = (const float*)d_in[4];
    const float* gin_b1 = (const float*)d_in[5];
    const float* gin_w2 = (const float*)d_in[6];
    const float* gin_b2 = (const float*)d_in[7];
    const float* wq     = (const float*)d_in[8];
    const float* bq     = (const float*)d_in[9];
    const float* wk     = (const float*)d_in[10];
    const float* bk     = (const float*)d_in[11];
    const float* wv     = (const float*)d_in[12];
    const float* bv     = (const float*)d_in[13];
    const float* nl_g   = (const float*)d_in[14];
    const float* nl_b   = (const float*)d_in[15];
    const float* na_g   = (const float*)d_in[16];
    const float* na_b   = (const float*)d_in[17];
    const float* no_g   = (const float*)d_in[18];
    const float* no_b   = (const float*)d_in[19];
    const float* ffn1_w = (const float*)d_in[20];
    const float* ffn1_b = (const float*)d_in[21];
    const float* ffn2_w = (const float*)d_in[22];
    const float* ffn2_b = (const float*)d_in[23];
    float* out = (float*)d_out;

    float* p_agg; cudaGetSymbolAddress((void**)&p_agg, g_agg);
    float* p_t1;  cudaGetSymbolAddress((void**)&p_t1,  g_t1);
    float* p_xl;  cudaGetSymbolAddress((void**)&p_xl,  g_xl);
    float* p_q;   cudaGetSymbolAddress((void**)&p_q,   g_q);
    float* p_k;   cudaGetSymbolAddress((void**)&p_k,   g_k);
    float* p_v;   cudaGetSymbolAddress((void**)&p_v,   g_v);
    float* p_xa;  cudaGetSymbolAddress((void**)&p_xa,  g_xa);
    float* p_hc;  cudaGetSymbolAddress((void**)&p_hc,  g_hc);
    float* p_xo;  cudaGetSymbolAddress((void**)&p_xo,  g_xo);
    float* p_ffn; cudaGetSymbolAddress((void**)&p_ffn, g_ffn);

    const int M = NND;
    dim3 g128(1, (M + 127) / 128);
    dim3 g256(2, (M + 127) / 128);
    const float scale = 0.25f;   // DH^-0.5, DH=16

    // 0) zero scratch
    zero_kernel<<<(NND * HD + 255) / 256, 256>>>();

    // 1) GINE aggregate
    msg_kernel<<<(NE * 32 + 255) / 256, 256>>>(h, eattr, src, dst);

    // 2) gin MLP:  t1 = relu((h+agg)@W1^T + b1) ; xl = h + t1@W2^T + b2
    sgemm_kernel<<<g128, 256>>>(h, p_agg, gin_w1, gin_b1, nullptr, p_t1, M, HD, HD, 1, 1.f);
    sgemm_kernel<<<g128, 256>>>(p_t1, nullptr, gin_w2, gin_b2, h, p_xl, M, HD, HD, 0, 1.f);
    stats_kernel<<<(M + 63) / 64, 128>>>(p_xl, nullptr, 0);

    // 3) q/k/v projections
    sgemm_kernel<<<g128, 256>>>(h, nullptr, wq, bq, nullptr, p_q, M, HD, HD, 0, scale);
    sgemm_kernel<<<g128, 256>>>(h, nullptr, wk, bk, nullptr, p_k, M, HD, HD, 0, 1.f);
    sgemm_kernel<<<g128, 256>>>(h, nullptr, wv, bv, nullptr, p_v, M, HD, HD, 0, 1.f);

    // 4) sparse softmax attention over edges
    score_kernel<<<(NE * NHD + 255) / 256, 256>>>(src, dst);
    psum_kernel <<<(NE * NHD + 255) / 256, 256>>>(src);
    avout_kernel<<<(NE * 32 + 255) / 256, 256>>>(src, dst);
    stats_kernel<<<(M + 63) / 64, 128>>>(p_xa, h, 1);    // xa = h + attn_out, + stats

    // 5) combine BNs
    combine_kernel<<<(NND * HD + 255) / 256, 256>>>(nl_g, nl_b, na_g, na_b);

    // 6) FFN + residual
    sgemm_kernel<<<g256, 256>>>(p_hc, nullptr, ffn1_w, ffn1_b, nullptr, p_ffn, M, 2 * HD, HD, 1, 1.f);
    sgemm_kernel<<<g128, 256>>>(p_ffn, nullptr, ffn2_w, ffn2_b, p_hc, p_xo, M, HD, 2 * HD, 0, 1.f);
    stats_kernel<<<(M + 63) / 64, 128>>>(p_xo, nullptr, 2);

    // 7) final BN -> output ; copy eattr to second output slot
    apply_kernel<<<(NND * HD + 255) / 256, 256>>>(no_g, no_b, out);
    cudaMemcpyAsync(out + (size_t)NND * HD, eattr, (size_t)NE * HD * sizeof(float),
                    cudaMemcpyDeviceToDevice, 0);
}

// round 4
// speedup vs baseline: 1.3603x; 1.3603x over previous
#include <cuda_runtime.h>
#include <cuda_bf16.h>
#include <cstdint>
#include <cstddef>

#define NND 50000
#define NE  500000
#define HD  128
#define NHD 8

// ---------------- scratch (device globals: allocation-free) ----------------
__device__ float    g_agg[NND * HD];
__device__ float    g_t1 [NND * HD];
__device__ float    g_xl [NND * HD];
__device__ float    g_q  [NND * HD];
__device__ float    g_k  [NND * HD];
__device__ float    g_v  [NND * HD];
__device__ float    g_xa [NND * HD];
__device__ float    g_hc [NND * HD];
__device__ float    g_xo [NND * HD];
__device__ float    g_ffn[NND * 2 * HD];
__device__ float    g_s  [NE * NHD];
__device__ unsigned g_mx [NND * NHD];
__device__ float    g_den[NND * NHD];
__device__ float    g_sum[3 * HD];
__device__ float    g_ssq[3 * HD];

// ---------------- helpers ----------------
__device__ __forceinline__ unsigned fenc(float f) {
    unsigned u = __float_as_uint(f);
    return (u & 0x80000000u) ? ~u : (u | 0x80000000u);
}
__device__ __forceinline__ float fdec(unsigned u) {
    return __uint_as_float((u & 0x80000000u) ? (u & 0x7fffffffu) : ~u);
}
__device__ __forceinline__ void red4(float* p, float4 v) {
    asm volatile("red.global.add.v4.f32 [%0], {%1,%2,%3,%4};"
                 :: "l"(p), "f"(v.x), "f"(v.y), "f"(v.z), "f"(v.w) : "memory");
}
__device__ __forceinline__ uint32_t smem_u32(const void* p) {
    uint32_t a;
    asm("{ .reg .u64 t; cvta.to.shared.u64 t, %1; cvt.u32.u64 %0, t; }" : "=r"(a) : "l"(p));
    return a;
}
__device__ __forceinline__ void ldm_x4(uint32_t* r, uint32_t addr) {
    asm volatile("ldmatrix.sync.aligned.m8n8.x4.shared.b16 {%0,%1,%2,%3}, [%4];"
                 : "=r"(r[0]), "=r"(r[1]), "=r"(r[2]), "=r"(r[3]) : "r"(addr));
}
__device__ __forceinline__ void ldm_x2(uint32_t* r, uint32_t addr) {
    asm volatile("ldmatrix.sync.aligned.m8n8.x2.shared.b16 {%0,%1}, [%2];"
                 : "=r"(r[0]), "=r"(r[1]) : "r"(addr));
}
__device__ __forceinline__ void mma16816(float* c, const uint32_t* a, const uint32_t* b) {
    asm volatile("mma.sync.aligned.m16n8k16.row.col.f32.bf16.bf16.f32 "
                 "{%0,%1,%2,%3}, {%4,%5,%6,%7}, {%8,%9}, {%0,%1,%2,%3};"
                 : "+f"(c[0]), "+f"(c[1]), "+f"(c[2]), "+f"(c[3])
                 : "r"(a[0]), "r"(a[1]), "r"(a[2]), "r"(a[3]), "r"(b[0]), "r"(b[1]));
}
__device__ __forceinline__ void split4(float4 a, uint2& hi, uint2& lo) {
    __nv_bfloat16 hx = __float2bfloat16_rn(a.x);
    __nv_bfloat16 hy = __float2bfloat16_rn(a.y);
    __nv_bfloat16 hz = __float2bfloat16_rn(a.z);
    __nv_bfloat16 hw = __float2bfloat16_rn(a.w);
    __nv_bfloat16 lx = __float2bfloat16_rn(a.x - __bfloat162float(hx));
    __nv_bfloat16 ly = __float2bfloat16_rn(a.y - __bfloat162float(hy));
    __nv_bfloat16 lz = __float2bfloat16_rn(a.z - __bfloat162float(hz));
    __nv_bfloat16 lw = __float2bfloat16_rn(a.w - __bfloat162float(hw));
    hi.x = ((uint32_t)__bfloat16_as_ushort(hy) << 16) | __bfloat16_as_ushort(hx);
    hi.y = ((uint32_t)__bfloat16_as_ushort(hw) << 16) | __bfloat16_as_ushort(hz);
    lo.x = ((uint32_t)__bfloat16_as_ushort(ly) << 16) | __bfloat16_as_ushort(lx);
    lo.y = ((uint32_t)__bfloat16_as_ushort(lw) << 16) | __bfloat16_as_ushort(lz);
}

// ---------------- zero scratch ----------------
__global__ void zero_kernel() {
    int i = blockIdx.x * blockDim.x + threadIdx.x;
    if (i < NND * HD) { g_agg[i] = 0.f; g_xa[i] = 0.f; }
    if (i < NND * NHD) { g_den[i] = 0.f; g_mx[i] = 0u; }
    if (i < 3 * HD)   { g_sum[i] = 0.f; g_ssq[i] = 0.f; }
}

// ---------------- GINE message ----------------
__global__ void msg_kernel(const float* __restrict__ h, const float* __restrict__ eattr,
                           const int* __restrict__ src, const int* __restrict__ dst) {
    int gid  = blockIdx.x * blockDim.x + threadIdx.x;
    int e    = gid >> 5;
    int lane = gid & 31;
    if (e >= NE) return;
    int sr = src[e], ds = dst[e];
    const float4 hv = *(const float4*)(h + (size_t)sr * HD + lane * 4);
    const float4 ev = *(const float4*)(eattr + (size_t)e * HD + lane * 4);
    float4 m;
    m.x = fmaxf(hv.x + ev.x, 0.f);
    m.y = fmaxf(hv.y + ev.y, 0.f);
    m.z = fmaxf(hv.z + ev.z, 0.f);
    m.w = fmaxf(hv.w + ev.w, 0.f);
    red4(&g_agg[(size_t)ds * HD + lane * 4], m);
}

// ---------------- bf16-split mma.sync GEMM ----------------
// C[M,Nn] = epi( (A(+A2))[M,Ktot] @ W[Nn,Ktot]^T + bias ) * scale ; relu? ; + addend?
// CTA tile 128x128, K-chunk 64. 8 warps: warp tile 32(M) x 64(N).
// SMEM tiles bf16 hi/lo, row stride 72 elems (144B, 16B-aligned, conflict-light).
#define SKW 72
#define TILE_B (128 * SKW * 2)              // 18432 bytes per tile
#define GEMM_SMEM (4 * TILE_B)              // 73728
__global__ __launch_bounds__(256, 1)
void mma_gemm_kernel(const float* __restrict__ A, const float* __restrict__ A2,
                     const float* __restrict__ W, const float* __restrict__ bias,
                     const float* __restrict__ addend, float* __restrict__ C,
                     int M, int Nn, int Ktot, int doRelu, float scale) {
    extern __shared__ char smem[];
    char* AHp = smem;
    char* ALp = smem + TILE_B;
    char* WHp = smem + 2 * TILE_B;
    char* WLp = smem + 3 * TILE_B;
    const uint32_t AHa = smem_u32(AHp), ALa = smem_u32(ALp);
    const uint32_t WHa = smem_u32(WHp), WLa = smem_u32(WLp);

    const int tid  = threadIdx.x;
    const int wid  = tid >> 5;
    const int lane = tid & 31;
    const int wm = wid & 3;          // M quadrant (0..3) -> rows wm*32..+31
    const int wn = wid >> 2;         // N half (0..1)     -> cols wn*64..+63
    const int row0 = blockIdx.y * 128;
    const int col0 = blockIdx.x * 128;

    float acc[2][8][4];
#pragma unroll
    for (int mt = 0; mt < 2; mt++)
#pragma unroll
        for (int nt = 0; nt < 8; nt++)
#pragma unroll
            for (int j = 0; j < 4; j++) acc[mt][nt][j] = 0.f;

    const int nChunks = Ktot >> 6;
    for (int kc = 0; kc < nChunks; kc++) {
        const int k0 = kc << 6;
        // cooperative load + split: A tile [128 x 64] fp32 -> AH/AL bf16
#pragma unroll
        for (int it = 0; it < 8; it++) {
            int i = tid + it * 256;              // 0..2047
            int r = i >> 4;
            int c = (i & 15) << 2;
            float4 a = make_float4(0.f, 0.f, 0.f, 0.f);
            int gr = row0 + r;
            if (gr < M) {
                a = *(const float4*)(A + (size_t)gr * Ktot + k0 + c);
                if (A2) {
                    float4 b = *(const float4*)(A2 + (size_t)gr * Ktot + k0 + c);
                    a.x += b.x; a.y += b.y; a.z += b.z; a.w += b.w;
                }
            }
            uint2 hi, lo;
            split4(a, hi, lo);
            *(uint2*)(AHp + r * (SKW * 2) + c * 2) = hi;
            *(uint2*)(ALp + r * (SKW * 2) + c * 2) = lo;
        }
        // W tile [128 x 64]
#pragma unroll
        for (int it = 0; it < 8; it++) {
            int i = tid + it * 256;
            int r = i >> 4;
            int c = (i & 15) << 2;
            float4 wv = *(const float4*)(W + (size_t)(col0 + r) * Ktot + k0 + c);
            uint2 hi, lo;
            split4(wv, hi, lo);
            *(uint2*)(WHp + r * (SKW * 2) + c * 2) = hi;
            *(uint2*)(WLp + r * (SKW * 2) + c * 2) = lo;
        }
        __syncthreads();

#pragma unroll
        for (int ks = 0; ks < 4; ks++) {
            const int kk = ks * 16;
            uint32_t ah[2][4], al[2][4];
#pragma unroll
            for (int mt = 0; mt < 2; mt++) {
                int r = wm * 32 + mt * 16 + (lane & 15);
                uint32_t off = (uint32_t)r * (SKW * 2) + kk * 2 + (lane >> 4) * 16;
                ldm_x4(ah[mt], AHa + off);
                ldm_x4(al[mt], ALa + off);
            }
            uint32_t bh[8][2], bl[8][2];
#pragma unroll
            for (int nt = 0; nt < 8; nt++) {
                int n = wn * 64 + nt * 8 + (lane & 7);
                uint32_t off = (uint32_t)n * (SKW * 2) + kk * 2 + ((lane >> 3) & 1) * 16;
                ldm_x2(bh[nt], WHa + off);
                ldm_x2(bl[nt], WLa + off);
            }
#pragma unroll
            for (int mt = 0; mt < 2; mt++)
#pragma unroll
                for (int nt = 0; nt < 8; nt++) {
                    mma16816(acc[mt][nt], ah[mt], bh[nt]);
                    mma16816(acc[mt][nt], al[mt], bh[nt]);
                    mma16816(acc[mt][nt], ah[mt], bl[nt]);
                }
        }
        __syncthreads();
    }

    // epilogue
    const int qr = lane >> 2;            // 0..7
    const int qc = (lane & 3) * 2;       // 0,2,4,6
#pragma unroll
    for (int mt = 0; mt < 2; mt++) {
#pragma unroll
        for (int half = 0; half < 2; half++) {
            int r = row0 + wm * 32 + mt * 16 + qr + half * 8;
            if (r >= M) continue;
#pragma unroll
            for (int nt = 0; nt < 8; nt++) {
                int c = col0 + wn * 64 + nt * 8 + qc;
                float v0 = (acc[mt][nt][half * 2 + 0] + bias[c + 0]) * scale;
                float v1 = (acc[mt][nt][half * 2 + 1] + bias[c + 1]) * scale;
                if (doRelu) { v0 = fmaxf(v0, 0.f); v1 = fmaxf(v1, 0.f); }
                if (addend) {
                    float2 ad = *(const float2*)(addend + (size_t)r * Nn + c);
                    v0 += ad.x; v1 += ad.y;
                }
                *(float2*)(C + (size_t)r * Nn + c) = make_float2(v0, v1);
            }
        }
    }
}

// ---------------- per-edge attention scores + segment max ----------------
__global__ void score_kernel(const int* __restrict__ src, const int* __restrict__ dst) {
    int i = blockIdx.x * blockDim.x + threadIdx.x;
    if (i >= NE * NHD) return;
    int e = i >> 3, hd = i & 7;
    int sr = src[e], ds = dst[e];
    const float4* qp = (const float4*)(g_q + (size_t)sr * HD + hd * 16);
    const float4* kp = (const float4*)(g_k + (size_t)ds * HD + hd * 16);
    float acc = 0.f;
#pragma unroll
    for (int j = 0; j < 4; j++) {
        float4 a = qp[j], b = kp[j];
        acc += a.x * b.x + a.y * b.y + a.z * b.z + a.w * b.w;
    }
    g_s[i] = acc;
    atomicMax(&g_mx[sr * NHD + hd], fenc(acc));
}

// ---------------- p = exp(s - m[src]) ; denom[src] += p ----------------
__global__ void psum_kernel(const int* __restrict__ src) {
    int i = blockIdx.x * blockDim.x + threadIdx.x;
    if (i >= NE * NHD) return;
    int e = i >> 3, hd = i & 7;
    int sr = src[e];
    float mm = fdec(g_mx[sr * NHD + hd]);
    float p = expf(g_s[i] - mm);
    g_s[i] = p;
    atomicAdd(&g_den[sr * NHD + hd], p);
}

// ---------------- out[src] += (p/denom[src]) * v[dst] ----------------
__global__ void avout_kernel(const int* __restrict__ src, const int* __restrict__ dst) {
    int gid  = blockIdx.x * blockDim.x + threadIdx.x;
    int e    = gid >> 5;
    int lane = gid & 31;
    if (e >= NE) return;
    int sr = src[e], ds = dst[e];
    int hd = lane >> 2;
    float attn = g_s[(size_t)e * NHD + hd] / g_den[sr * NHD + hd];
    float4 vv = *(const float4*)(g_v + (size_t)ds * HD + lane * 4);
    vv.x *= attn; vv.y *= attn; vv.z *= attn; vv.w *= attn;
    red4(&g_xa[(size_t)sr * HD + lane * 4], vv);
}

// ---------------- BN statistics ----------------
__global__ void stats_kernel(float* __restrict__ x, const float* __restrict__ add, int slot) {
    int c  = threadIdx.x;
    int r0 = blockIdx.x * 64;
    float s = 0.f, ss = 0.f;
    for (int i = 0; i < 64; i++) {
        int r = r0 + i;
        if (r < NND) {
            size_t idx = (size_t)r * HD + c;
            float v = x[idx];
            if (add) { v += add[idx]; x[idx] = v; }
            s += v; ss += v * v;
        }
    }
    atomicAdd(&g_sum[slot * HD + c], s);
    atomicAdd(&g_ssq[slot * HD + c], ss);
}

// ---------------- hc = bn0(xl) + bn1(xa) ----------------
__global__ void combine_kernel(const float* __restrict__ nl_g, const float* __restrict__ nl_b,
                               const float* __restrict__ na_g, const float* __restrict__ na_b) {
    int i = blockIdx.x * blockDim.x + threadIdx.x;
    if (i >= NND * HD) return;
    int c = i & (HD - 1);
    const float invN = 1.f / (float)NND;
    float mu0 = g_sum[c] * invN;
    float v0  = g_ssq[c] * invN - mu0 * mu0;
    float i0  = rsqrtf(v0 + 1e-5f);
    float mu1 = g_sum[HD + c] * invN;
    float v1  = g_ssq[HD + c] * invN - mu1 * mu1;
    float i1  = rsqrtf(v1 + 1e-5f);
    float a = (g_xl[i] - mu0) * i0 * nl_g[c] + nl_b[c];
    float b = (g_xa[i] - mu1) * i1 * na_g[c] + na_b[c];
    g_hc[i] = a + b;
}

// ---------------- out = bn2(xo) ----------------
__global__ void apply_kernel(const float* __restrict__ no_g, const float* __restrict__ no_b,
                             float* __restrict__ out) {
    int i = blockIdx.x * blockDim.x + threadIdx.x;
    if (i >= NND * HD) return;
    int c = i & (HD - 1);
    const float invN = 1.f / (float)NND;
    float mu = g_sum[2 * HD + c] * invN;
    float v  = g_ssq[2 * HD + c] * invN - mu * mu;
    float iv = rsqrtf(v + 1e-5f);
    out[i] = (g_xo[i] - mu) * iv * no_g[c] + no_b[c];
}

// ---------------- host launcher ----------------
extern "C" void kernel_launch(void* const* d_in, const int* in_sizes, int n_in,
                              void* d_out, int out_size) {
    const float* h      = (const float*)d_in[0];
    const float* eattr  = (const float*)d_in[1];
    const int*   src    = (const int*)  d_in[2];
    const int*   dst    = (const int*)  d_in[3];
    const float* gin_w1 = (const float*)d_in[4];
    const float* gin_b1 = (const float*)d_in[5];
    const float* gin_w2 = (const float*)d_in[6];
    const float* gin_b2 = (const float*)d_in[7];
    const float* wq     = (const float*)d_in[8];
    const float* bq     = (const float*)d_in[9];
    const float* wk     = (const float*)d_in[10];
    const float* bk     = (const float*)d_in[11];
    const float* wv     = (const float*)d_in[12];
    const float* bv     = (const float*)d_in[13];
    const float* nl_g   = (const float*)d_in[14];
    const float* nl_b   = (const float*)d_in[15];
    const float* na_g   = (const float*)d_in[16];
    const float* na_b   = (const float*)d_in[17];
    const float* no_g   = (const float*)d_in[18];
    const float* no_b   = (const float*)d_in[19];
    const float* ffn1_w = (const float*)d_in[20];
    const float* ffn1_b = (const float*)d_in[21];
    const float* ffn2_w = (const float*)d_in[22];
    const float* ffn2_b = (const float*)d_in[23];
    float* out = (float*)d_out;

    float* p_agg; cudaGetSymbolAddress((void**)&p_agg, g_agg);
    float* p_t1;  cudaGetSymbolAddress((void**)&p_t1,  g_t1);
    float* p_xl;  cudaGetSymbolAddress((void**)&p_xl,  g_xl);
    float* p_q;   cudaGetSymbolAddress((void**)&p_q,   g_q);
    float* p_k;   cudaGetSymbolAddress((void**)&p_k,   g_k);
    float* p_v;   cudaGetSymbolAddress((void**)&p_v,   g_v);
    float* p_xa;  cudaGetSymbolAddress((void**)&p_xa,  g_xa);
    float* p_hc;  cudaGetSymbolAddress((void**)&p_hc,  g_hc);
    float* p_xo;  cudaGetSymbolAddress((void**)&p_xo,  g_xo);
    float* p_ffn; cudaGetSymbolAddress((void**)&p_ffn, g_ffn);

    cudaFuncSetAttribute(mma_gemm_kernel, cudaFuncAttributeMaxDynamicSharedMemorySize, GEMM_SMEM);

    const int M = NND;
    const int MT = (M + 127) / 128;       // 391
    dim3 g1(1, MT), g2(2, MT);
    const float scale = 0.25f;            // DH^-0.5, DH=16

    zero_kernel<<<(NND * HD + 255) / 256, 256>>>();
    msg_kernel<<<(NE * 32 + 255) / 256, 256>>>(h, eattr, src, dst);

    mma_gemm_kernel<<<g1, 256, GEMM_SMEM>>>(h, p_agg, gin_w1, gin_b1, nullptr, p_t1, M, HD, HD, 1, 1.f);
    mma_gemm_kernel<<<g1, 256, GEMM_SMEM>>>(p_t1, nullptr, gin_w2, gin_b2, h, p_xl, M, HD, HD, 0, 1.f);
    stats_kernel<<<(M + 63) / 64, 128>>>(p_xl, nullptr, 0);

    mma_gemm_kernel<<<g1, 256, GEMM_SMEM>>>(h, nullptr, wq, bq, nullptr, p_q, M, HD, HD, 0, scale);
    mma_gemm_kernel<<<g1, 256, GEMM_SMEM>>>(h, nullptr, wk, bk, nullptr, p_k, M, HD, HD, 0, 1.f);
    mma_gemm_kernel<<<g1, 256, GEMM_SMEM>>>(h, nullptr, wv, bv, nullptr, p_v, M, HD, HD, 0, 1.f);

    score_kernel<<<(NE * NHD + 255) / 256, 256>>>(src, dst);
    psum_kernel <<<(NE * NHD + 255) / 256, 256>>>(src);
    avout_kernel<<<(NE * 32 + 255) / 256, 256>>>(src, dst);
    stats_kernel<<<(M + 63) / 64, 128>>>(p_xa, h, 1);

    combine_kernel<<<(NND * HD + 255) / 256, 256>>>(nl_g, nl_b, na_g, na_b);

    mma_gemm_kernel<<<g2, 256, GEMM_SMEM>>>(p_hc, nullptr, ffn1_w, ffn1_b, nullptr, p_ffn, M, 2 * HD, HD, 1, 1.f);
    mma_gemm_kernel<<<g1, 256, GEMM_SMEM>>>(p_ffn, nullptr, ffn2_w, ffn2_b, p_hc, p_xo, M, HD, 2 * HD, 0, 1.f);
    stats_kernel<<<(M + 63) / 64, 128>>>(p_xo, nullptr, 2);

    apply_kernel<<<(NND * HD + 255) / 256, 256>>>(no_g, no_b, out);
    cudaMemcpyAsync(out + (size_t)NND * HD, eattr, (size_t)NE * HD * sizeof(float),
                    cudaMemcpyDeviceToDevice, 0);
}

// round 6
// speedup vs baseline: 1.4582x; 1.0720x over previous
#include <cuda_runtime.h>
#include <cuda_bf16.h>
#include <cstdint>
#include <cstddef>

#define NND 50000
#define NE  500000
#define HD  128
#define NHD 8

// ---------------- scratch (device globals: allocation-free) ----------------
__device__ float g_agg[NND * HD];
__device__ float g_t1 [NND * HD];
__device__ float g_xl [NND * HD];
__device__ float g_q  [NND * HD];
__device__ float g_k  [NND * HD];
__device__ float g_v  [NND * HD];
__device__ float g_xa [NND * HD];
__device__ float g_hc [NND * HD];
__device__ float g_xo [NND * HD];
__device__ float g_ffn[NND * 2 * HD];
__device__ float g_den[NND * NHD];
__device__ float g_sum[3 * HD];
__device__ float g_ssq[3 * HD];

// ---------------- helpers ----------------
__device__ __forceinline__ void red4(float* p, float4 v) {
    asm volatile("red.global.add.v4.f32 [%0], {%1,%2,%3,%4};"
                 :: "l"(p), "f"(v.x), "f"(v.y), "f"(v.z), "f"(v.w) : "memory");
}
__device__ __forceinline__ uint32_t smem_u32(const void* p) {
    uint32_t a;
    asm("{ .reg .u64 t; cvta.to.shared.u64 t, %1; cvt.u32.u64 %0, t; }" : "=r"(a) : "l"(p));
    return a;
}
__device__ __forceinline__ void ldm_x4(uint32_t* r, uint32_t addr) {
    asm volatile("ldmatrix.sync.aligned.m8n8.x4.shared.b16 {%0,%1,%2,%3}, [%4];"
                 : "=r"(r[0]), "=r"(r[1]), "=r"(r[2]), "=r"(r[3]) : "r"(addr));
}
__device__ __forceinline__ void ldm_x2(uint32_t* r, uint32_t addr) {
    asm volatile("ldmatrix.sync.aligned.m8n8.x2.shared.b16 {%0,%1}, [%2];"
                 : "=r"(r[0]), "=r"(r[1]) : "r"(addr));
}
__device__ __forceinline__ void mma16816(float* c, const uint32_t* a, const uint32_t* b) {
    asm volatile("mma.sync.aligned.m16n8k16.row.col.f32.bf16.bf16.f32 "
                 "{%0,%1,%2,%3}, {%4,%5,%6,%7}, {%8,%9}, {%0,%1,%2,%3};"
                 : "+f"(c[0]), "+f"(c[1]), "+f"(c[2]), "+f"(c[3])
                 : "r"(a[0]), "r"(a[1]), "r"(a[2]), "r"(a[3]), "r"(b[0]), "r"(b[1]));
}
__device__ __forceinline__ void split4(float4 a, uint2& hi, uint2& lo) {
    __nv_bfloat16 hx = __float2bfloat16_rn(a.x);
    __nv_bfloat16 hy = __float2bfloat16_rn(a.y);
    __nv_bfloat16 hz = __float2bfloat16_rn(a.z);
    __nv_bfloat16 hw = __float2bfloat16_rn(a.w);
    __nv_bfloat16 lx = __float2bfloat16_rn(a.x - __bfloat162float(hx));
    __nv_bfloat16 ly = __float2bfloat16_rn(a.y - __bfloat162float(hy));
    __nv_bfloat16 lz = __float2bfloat16_rn(a.z - __bfloat162float(hz));
    __nv_bfloat16 lw = __float2bfloat16_rn(a.w - __bfloat162float(hw));
    hi.x = ((uint32_t)__bfloat16_as_ushort(hy) << 16) | __bfloat16_as_ushort(hx);
    hi.y = ((uint32_t)__bfloat16_as_ushort(hw) << 16) | __bfloat16_as_ushort(hz);
    lo.x = ((uint32_t)__bfloat16_as_ushort(ly) << 16) | __bfloat16_as_ushort(lx);
    lo.y = ((uint32_t)__bfloat16_as_ushort(lw) << 16) | __bfloat16_as_ushort(lz);
}

// ---------------- zero scratch ----------------
__global__ void zero_kernel() {
    int i = blockIdx.x * blockDim.x + threadIdx.x;
    if (i < NND * HD) { g_agg[i] = 0.f; g_xa[i] = 0.f; }
    if (i < NND * NHD) g_den[i] = 0.f;
    if (i < 3 * HD)   { g_sum[i] = 0.f; g_ssq[i] = 0.f; }
}

// ---------------- GINE message ----------------
__global__ void msg_kernel(const float* __restrict__ h, const float* __restrict__ eattr,
                           const int* __restrict__ src, const int* __restrict__ dst) {
    int gid  = blockIdx.x * blockDim.x + threadIdx.x;
    int e    = gid >> 5;
    int lane = gid & 31;
    if (e >= NE) return;
    int sr = src[e], ds = dst[e];
    const float4 hv = *(const float4*)(h + (size_t)sr * HD + lane * 4);
    const float4 ev = *(const float4*)(eattr + (size_t)e * HD + lane * 4);
    float4 m;
    m.x = fmaxf(hv.x + ev.x, 0.f);
    m.y = fmaxf(hv.y + ev.y, 0.f);
    m.z = fmaxf(hv.z + ev.z, 0.f);
    m.w = fmaxf(hv.w + ev.w, 0.f);
    red4(&g_agg[(size_t)ds * HD + lane * 4], m);
}

// ---------------- bf16-split mma.sync GEMM ----------------
// CTA: 128 threads, tile 64(M) x 128(N), K-chunk 64. Warp tile 32x64.
// Multi-W: blockIdx.x = sel * (Nn/128) + colblk ; W/bias/C/scale chosen by sel.
#define SKW 72
#define A_TILE_B (64  * SKW * 2)            // 9216
#define W_TILE_B (128 * SKW * 2)            // 18432
#define GEMM_SMEM (2 * A_TILE_B + 2 * W_TILE_B)   // 55296
__global__ __launch_bounds__(128, 2)
void mma_gemm_kernel(const float* __restrict__ A, const float* __restrict__ A2,
                     const float* __restrict__ W0, const float* __restrict__ W1,
                     const float* __restrict__ W2,
                     const float* __restrict__ b0, const float* __restrict__ b1,
                     const float* __restrict__ b2,
                     const float* __restrict__ addend,
                     float* __restrict__ C0, float* __restrict__ C1, float* __restrict__ C2,
                     int M, int Nn, int Ktot, int doRelu,
                     float s0, float s1, float s2) {
    extern __shared__ char smem[];
    char* AHp = smem;
    char* ALp = smem + A_TILE_B;
    char* WHp = smem + 2 * A_TILE_B;
    char* WLp = smem + 2 * A_TILE_B + W_TILE_B;
    const uint32_t AHa = smem_u32(AHp), ALa = smem_u32(ALp);
    const uint32_t WHa = smem_u32(WHp), WLa = smem_u32(WLp);

    const int nColBlk = Nn >> 7;
    const int sel    = blockIdx.x / nColBlk;
    const int colblk = blockIdx.x - sel * nColBlk;
    const float* W    = (sel == 0) ? W0 : (sel == 1) ? W1 : W2;
    const float* bias = (sel == 0) ? b0 : (sel == 1) ? b1 : b2;
    float* C          = (sel == 0) ? C0 : (sel == 1) ? C1 : C2;
    const float scale = (sel == 0) ? s0 : (sel == 1) ? s1 : s2;

    const int tid  = threadIdx.x;
    const int wid  = tid >> 5;
    const int lane = tid & 31;
    const int wm = wid & 1;          // M half (0..1) -> rows wm*32..+31
    const int wn = wid >> 1;         // N half (0..1) -> cols wn*64..+63
    const int row0 = blockIdx.y * 64;
    const int col0 = colblk * 128;

    float acc[2][8][4];
#pragma unroll
    for (int mt = 0; mt < 2; mt++)
#pragma unroll
        for (int nt = 0; nt < 8; nt++)
#pragma unroll
            for (int j = 0; j < 4; j++) acc[mt][nt][j] = 0.f;

    const int nChunks = Ktot >> 6;
    for (int kc = 0; kc < nChunks; kc++) {
        const int k0 = kc << 6;
        // A tile [64 x 64] fp32 -> AH/AL (1024 float4, 8 per thread)
#pragma unroll
        for (int it = 0; it < 8; it++) {
            int i = tid + it * 128;
            int r = i >> 4;
            int c = (i & 15) << 2;
            float4 a = make_float4(0.f, 0.f, 0.f, 0.f);
            int gr = row0 + r;
            if (gr < M) {
                a = *(const float4*)(A + (size_t)gr * Ktot + k0 + c);
                if (A2) {
                    float4 b = *(const float4*)(A2 + (size_t)gr * Ktot + k0 + c);
                    a.x += b.x; a.y += b.y; a.z += b.z; a.w += b.w;
                }
            }
            uint2 hi, lo;
            split4(a, hi, lo);
            *(uint2*)(AHp + r * (SKW * 2) + c * 2) = hi;
            *(uint2*)(ALp + r * (SKW * 2) + c * 2) = lo;
        }
        // W tile [128 x 64] (2048 float4, 16 per thread)
#pragma unroll
        for (int it = 0; it < 16; it++) {
            int i = tid + it * 128;
            int r = i >> 4;
            int c = (i & 15) << 2;
            float4 wv = *(const float4*)(W + (size_t)(col0 + r) * Ktot + k0 + c);
            uint2 hi, lo;
            split4(wv, hi, lo);
            *(uint2*)(WHp + r * (SKW * 2) + c * 2) = hi;
            *(uint2*)(WLp + r * (SKW * 2) + c * 2) = lo;
        }
        __syncthreads();

#pragma unroll
        for (int ks = 0; ks < 4; ks++) {
            const int kk = ks * 16;
            uint32_t ah[2][4], al[2][4];
#pragma unroll
            for (int mt = 0; mt < 2; mt++) {
                int r = wm * 32 + mt * 16 + (lane & 15);
                uint32_t off = (uint32_t)r * (SKW * 2) + kk * 2 + (lane >> 4) * 16;
                ldm_x4(ah[mt], AHa + off);
                ldm_x4(al[mt], ALa + off);
            }
            uint32_t bh[8][2], bl[8][2];
#pragma unroll
            for (int nt = 0; nt < 8; nt++) {
                int n = wn * 64 + nt * 8 + (lane & 7);
                uint32_t off = (uint32_t)n * (SKW * 2) + kk * 2 + ((lane >> 3) & 1) * 16;
                ldm_x2(bh[nt], WHa + off);
                ldm_x2(bl[nt], WLa + off);
            }
#pragma unroll
            for (int mt = 0; mt < 2; mt++)
#pragma unroll
                for (int nt = 0; nt < 8; nt++) {
                    mma16816(acc[mt][nt], ah[mt], bh[nt]);
                    mma16816(acc[mt][nt], al[mt], bh[nt]);
                    mma16816(acc[mt][nt], ah[mt], bl[nt]);
                }
        }
        __syncthreads();
    }

    // epilogue
    const int qr = lane >> 2;
    const int qc = (lane & 3) * 2;
#pragma unroll
    for (int mt = 0; mt < 2; mt++) {
#pragma unroll
        for (int half = 0; half < 2; half++) {
            int r = row0 + wm * 32 + mt * 16 + qr + half * 8;
            if (r >= M) continue;
#pragma unroll
            for (int nt = 0; nt < 8; nt++) {
                int c = col0 + wn * 64 + nt * 8 + qc;
                float v0 = (acc[mt][nt][half * 2 + 0] + bias[c + 0]) * scale;
                float v1 = (acc[mt][nt][half * 2 + 1] + bias[c + 1]) * scale;
                if (doRelu) { v0 = fmaxf(v0, 0.f); v1 = fmaxf(v1, 0.f); }
                if (addend) {
                    float2 ad = *(const float2*)(addend + (size_t)r * Nn + c);
                    v0 += ad.x; v1 += ad.y;
                }
                *(float2*)(C + (size_t)r * Nn + c) = make_float2(v0, v1);
            }
        }
    }
}

// ---------------- fused edge attention: p=exp(q.k); den[src]+=p; xa[src]+=p*v[dst] ----------------
__global__ void attn_edge_kernel(const int* __restrict__ src, const int* __restrict__ dst) {
    int gid  = blockIdx.x * blockDim.x + threadIdx.x;
    int e    = gid >> 5;
    int lane = gid & 31;
    if (e >= NE) return;
    int sr = src[e], ds = dst[e];
    const float4 qv = *(const float4*)(g_q + (size_t)sr * HD + lane * 4);
    const float4 kv = *(const float4*)(g_k + (size_t)ds * HD + lane * 4);
    float part = qv.x * kv.x + qv.y * kv.y + qv.z * kv.z + qv.w * kv.w;
    part += __shfl_xor_sync(0xffffffffu, part, 1);
    part += __shfl_xor_sync(0xffffffffu, part, 2);   // per-head dot (4-lane group)
    float p = __expf(part);
    if ((lane & 3) == 0)
        atomicAdd(&g_den[sr * NHD + (lane >> 2)], p);
    float4 vv = *(const float4*)(g_v + (size_t)ds * HD + lane * 4);
    vv.x *= p; vv.y *= p; vv.z *= p; vv.w *= p;
    red4(&g_xa[(size_t)sr * HD + lane * 4], vv);
}

// ---------------- BN statistics (modes: plain / add / divide-by-den + add) ----------------
__global__ void stats_kernel(float* __restrict__ x, const float* __restrict__ add,
                             int slot, int divmode) {
    int c  = threadIdx.x;
    int r0 = blockIdx.x * 64;
    int hd = c >> 4;
    float s = 0.f, ss = 0.f;
    for (int i = 0; i < 64; i++) {
        int r = r0 + i;
        if (r < NND) {
            size_t idx = (size_t)r * HD + c;
            float v = x[idx];
            if (divmode) {
                float d = g_den[r * NHD + hd];
                v = (d > 0.f) ? (v / d) : 0.f;   // isolated node: empty segment -> 0
            }
            if (add) v += add[idx];
            if (add || divmode) x[idx] = v;
            s += v; ss += v * v;
        }
    }
    atomicAdd(&g_sum[slot * HD + c], s);
    atomicAdd(&g_ssq[slot * HD + c], ss);
}

// ---------------- hc = bn0(xl) + bn1(xa) ----------------
__global__ void combine_kernel(const float* __restrict__ nl_g, const float* __restrict__ nl_b,
                               const float* __restrict__ na_g, const float* __restrict__ na_b) {
    int i = blockIdx.x * blockDim.x + threadIdx.x;
    if (i >= NND * HD) return;
    int c = i & (HD - 1);
    const float invN = 1.f / (float)NND;
    float mu0 = g_sum[c] * invN;
    float v0  = g_ssq[c] * invN - mu0 * mu0;
    float i0  = rsqrtf(v0 + 1e-5f);
    float mu1 = g_sum[HD + c] * invN;
    float v1  = g_ssq[HD + c] * invN - mu1 * mu1;
    float i1  = rsqrtf(v1 + 1e-5f);
    float a = (g_xl[i] - mu0) * i0 * nl_g[c] + nl_b[c];
    float b = (g_xa[i] - mu1) * i1 * na_g[c] + na_b[c];
    g_hc[i] = a + b;
}

// ---------------- out = bn2(xo) ----------------
__global__ void apply_kernel(const float* __restrict__ no_g, const float* __restrict__ no_b,
                             float* __restrict__ out) {
    int i = blockIdx.x * blockDim.x + threadIdx.x;
    if (i >= NND * HD) return;
    int c = i & (HD - 1);
    const float invN = 1.f / (float)NND;
    float mu = g_sum[2 * HD + c] * invN;
    float v  = g_ssq[2 * HD + c] * invN - mu * mu;
    float iv = rsqrtf(v + 1e-5f);
    out[i] = (g_xo[i] - mu) * iv * no_g[c] + no_b[c];
}

// ---------------- host launcher ----------------
extern "C" void kernel_launch(void* const* d_in, const int* in_sizes, int n_in,
                              void* d_out, int out_size) {
    const float* h      = (const float*)d_in[0];
    const float* eattr  = (const float*)d_in[1];
    const int*   src    = (const int*)  d_in[2];
    const int*   dst    = (const int*)  d_in[3];
    const float* gin_w1 = (const float*)d_in[4];
    const float* gin_b1 = (const float*)d_in[5];
    const float* gin_w2 = (const float*)d_in[6];
    const float* gin_b2 = (const float*)d_in[7];
    const float* wq     = (const float*)d_in[8];
    const float* bq     = (const float*)d_in[9];
    const float* wk     = (const float*)d_in[10];
    const float* bk     = (const float*)d_in[11];
    const float* wv     = (const float*)d_in[12];
    const float* bv     = (const float*)d_in[13];
    const float* nl_g   = (const float*)d_in[14];
    const float* nl_b   = (const float*)d_in[15];
    const float* na_g   = (const float*)d_in[16];
    const float* na_b   = (const float*)d_in[17];
    const float* no_g   = (const float*)d_in[18];
    const float* no_b   = (const float*)d_in[19];
    const float* ffn1_w = (const float*)d_in[20];
    const float* ffn1_b = (const float*)d_in[21];
    const float* ffn2_w = (const float*)d_in[22];
    const float* ffn2_b = (const float*)d_in[23];
    float* out = (float*)d_out;

    float* p_agg; cudaGetSymbolAddress((void**)&p_agg, g_agg);
    float* p_t1;  cudaGetSymbolAddress((void**)&p_t1,  g_t1);
    float* p_xl;  cudaGetSymbolAddress((void**)&p_xl,  g_xl);
    float* p_q;   cudaGetSymbolAddress((void**)&p_q,   g_q);
    float* p_k;   cudaGetSymbolAddress((void**)&p_k,   g_k);
    float* p_v;   cudaGetSymbolAddress((void**)&p_v,   g_v);
    float* p_xa;  cudaGetSymbolAddress((void**)&p_xa,  g_xa);
    float* p_hc;  cudaGetSymbolAddress((void**)&p_hc,  g_hc);
    float* p_xo;  cudaGetSymbolAddress((void**)&p_xo,  g_xo);
    float* p_ffn; cudaGetSymbolAddress((void**)&p_ffn, g_ffn);

    cudaFuncSetAttribute(mma_gemm_kernel, cudaFuncAttributeMaxDynamicSharedMemorySize, GEMM_SMEM);

    const int M  = NND;
    const int MT = (M + 63) / 64;         // 782
    const float scale = 0.25f;            // DH^-0.5, DH=16

    zero_kernel<<<(NND * HD + 255) / 256, 256>>>();
    msg_kernel<<<(NE * 32 + 255) / 256, 256>>>(h, eattr, src, dst);

    // gin MLP
    mma_gemm_kernel<<<dim3(1, MT), 128, GEMM_SMEM>>>(
        h, p_agg, gin_w1, gin_w1, gin_w1, gin_b1, gin_b1, gin_b1,
        nullptr, p_t1, p_t1, p_t1, M, HD, HD, 1, 1.f, 1.f, 1.f);
    mma_gemm_kernel<<<dim3(1, MT), 128, GEMM_SMEM>>>(
        p_t1, nullptr, gin_w2, gin_w2, gin_w2, gin_b2, gin_b2, gin_b2,
        h, p_xl, p_xl, p_xl, M, HD, HD, 0, 1.f, 1.f, 1.f);
    stats_kernel<<<(M + 63) / 64, 128>>>(p_xl, nullptr, 0, 0);

    // fused q/k/v projections (sel = blockIdx.x)
    mma_gemm_kernel<<<dim3(3, MT), 128, GEMM_SMEM>>>(
        h, nullptr, wq, wk, wv, bq, bk, bv,
        nullptr, p_q, p_k, p_v, M, HD, HD, 0, scale, 1.f, 1.f);

    // fused sparse softmax attention (single edge pass, deferred normalization)
    attn_edge_kernel<<<(NE * 32 + 255) / 256, 256>>>(src, dst);
    stats_kernel<<<(M + 63) / 64, 128>>>(p_xa, h, 1, 1);   // xa = h + xa/den, + stats

    combine_kernel<<<(NND * HD + 255) / 256, 256>>>(nl_g, nl_b, na_g, na_b);

    // FFN + residual
    mma_gemm_kernel<<<dim3(2, MT), 128, GEMM_SMEM>>>(
        p_hc, nullptr, ffn1_w, ffn1_w, ffn1_w, ffn1_b, ffn1_b, ffn1_b,
        nullptr, p_ffn, p_ffn, p_ffn, M, 2 * HD, HD, 1, 1.f, 1.f, 1.f);
    mma_gemm_kernel<<<dim3(1, MT), 128, GEMM_SMEM>>>(
        p_ffn, nullptr, ffn2_w, ffn2_w, ffn2_w, ffn2_b, ffn2_b, ffn2_b,
        p_hc, p_xo, p_xo, p_xo, M, HD, 2 * HD, 0, 1.f, 1.f, 1.f);
    stats_kernel<<<(M + 63) / 64, 128>>>(p_xo, nullptr, 2, 0);

    apply_kernel<<<(NND * HD + 255) / 256, 256>>>(no_g, no_b, out);
    cudaMemcpyAsync(out + (size_t)NND * HD, eattr, (size_t)NE * HD * sizeof(float),
                    cudaMemcpyDeviceToDevice, 0);
}

// round 7
// speedup vs baseline: 1.7396x; 1.1929x over previous
#include <cuda_runtime.h>
#include <cuda_bf16.h>
#include <cstdint>
#include <cstddef>

#define NND 50000
#define NE  500000
#define HD  128
#define NHD 8

// ---------------- scratch (device globals: allocation-free) ----------------
__device__ float g_agg[NND * HD];
__device__ float g_t1 [NND * HD];
__device__ float g_xl [NND * HD];
__device__ float g_q  [NND * HD];
__device__ float g_k  [NND * HD];
__device__ float g_v  [NND * HD];
__device__ float g_xa [NND * HD];
__device__ float g_hc [NND * HD];
__device__ float g_xo [NND * HD];
__device__ float g_ffn[NND * 2 * HD];
__device__ float g_den[NND * NHD];
__device__ float g_sum[3 * HD];
__device__ float g_ssq[3 * HD];

// ---------------- helpers ----------------
__device__ __forceinline__ void red4(float* p, float4 v) {
    asm volatile("red.global.add.v4.f32 [%0], {%1,%2,%3,%4};"
                 :: "l"(p), "f"(v.x), "f"(v.y), "f"(v.z), "f"(v.w) : "memory");
}
__device__ __forceinline__ uint32_t smem_u32(const void* p) {
    uint32_t a;
    asm("{ .reg .u64 t; cvta.to.shared.u64 t, %1; cvt.u32.u64 %0, t; }" : "=r"(a) : "l"(p));
    return a;
}
__device__ __forceinline__ void cp16(uint32_t dst, const float* src, int nbytes) {
    asm volatile("cp.async.ca.shared.global [%0], [%1], 16, %2;"
                 :: "r"(dst), "l"(__cvta_generic_to_global(src)), "r"(nbytes) : "memory");
}
__device__ __forceinline__ uint32_t f2tf32(float f) {
    uint32_t r;
    asm("cvt.rna.tf32.f32 %0, %1;" : "=r"(r) : "f"(f));
    return r;
}
__device__ __forceinline__ void mma_tf32(float* c, const uint32_t* a, const uint32_t* b) {
    asm volatile("mma.sync.aligned.m16n8k8.row.col.f32.tf32.tf32.f32 "
                 "{%0,%1,%2,%3}, {%4,%5,%6,%7}, {%8,%9}, {%0,%1,%2,%3};"
                 : "+f"(c[0]), "+f"(c[1]), "+f"(c[2]), "+f"(c[3])
                 : "r"(a[0]), "r"(a[1]), "r"(a[2]), "r"(a[3]), "r"(b[0]), "r"(b[1]));
}

// ---------------- init scratch (g_agg = h : folds the GINE self-term) ----------------
__global__ void zero_kernel(const float* __restrict__ h) {
    int i = blockIdx.x * blockDim.x + threadIdx.x;
    if (i < NND * HD) { g_agg[i] = h[i]; g_xa[i] = 0.f; }
    if (i < NND * NHD) g_den[i] = 0.f;
    if (i < 3 * HD)   { g_sum[i] = 0.f; g_ssq[i] = 0.f; }
}

// ---------------- GINE message + eattr passthrough to output ----------------
__global__ void msg_kernel(const float* __restrict__ h, const float* __restrict__ eattr,
                           const int* __restrict__ src, const int* __restrict__ dst,
                           float* __restrict__ out_e) {
    int gid  = blockIdx.x * blockDim.x + threadIdx.x;
    int e    = gid >> 5;
    int lane = gid & 31;
    if (e >= NE) return;
    int sr = src[e], ds = dst[e];
    const float4 hv = *(const float4*)(h + (size_t)sr * HD + lane * 4);
    const float4 ev = *(const float4*)(eattr + (size_t)e * HD + lane * 4);
    *(float4*)(out_e + (size_t)e * HD + lane * 4) = ev;   // fused eattr copy-out
    float4 m;
    m.x = fmaxf(hv.x + ev.x, 0.f);
    m.y = fmaxf(hv.y + ev.y, 0.f);
    m.z = fmaxf(hv.z + ev.z, 0.f);
    m.w = fmaxf(hv.w + ev.w, 0.f);
    red4(&g_agg[(size_t)ds * HD + lane * 4], m);
}

// ---------------- tf32 mma.sync GEMM, cp.async 2-stage pipeline ----------------
// C[M,Nn] = epi( A[M,Ktot] @ W[Nn,Ktot]^T + bias ) * scale ; relu? ; + addend?
// CTA: 128 threads, tile 64(M) x 128(N), K-chunk 32, warp tile 32x64.
// SMEM fp32 tiles, row stride 36 floats (conflict-free frag lds).
#define AS_F (64 * 36)                      // floats per A stage
#define WS_F (128 * 36)
#define GEMM_SMEM ((2 * AS_F + 2 * WS_F) * 4)   // 55296 B
__global__ __launch_bounds__(128, 3)
void mma_gemm_kernel(const float* __restrict__ A,
                     const float* __restrict__ W0, const float* __restrict__ W1,
                     const float* __restrict__ W2,
                     const float* __restrict__ b0, const float* __restrict__ b1,
                     const float* __restrict__ b2,
                     const float* __restrict__ addend,
                     float* __restrict__ C0, float* __restrict__ C1, float* __restrict__ C2,
                     int M, int Nn, int Ktot, int doRelu,
                     float s0, float s1, float s2) {
    extern __shared__ float smf[];
    float* Asm[2] = { smf,          smf + AS_F };
    float* Wsm[2] = { smf + 2*AS_F, smf + 2*AS_F + WS_F };
    const uint32_t aB[2] = { smem_u32(Asm[0]), smem_u32(Asm[1]) };
    const uint32_t wB[2] = { smem_u32(Wsm[0]), smem_u32(Wsm[1]) };

    const int nColBlk = Nn >> 7;
    const int sel    = blockIdx.x / nColBlk;
    const int colblk = blockIdx.x - sel * nColBlk;
    const float* W    = (sel == 0) ? W0 : (sel == 1) ? W1 : W2;
    const float* bias = (sel == 0) ? b0 : (sel == 1) ? b1 : b2;
    float* C          = (sel == 0) ? C0 : (sel == 1) ? C1 : C2;
    const float scale = (sel == 0) ? s0 : (sel == 1) ? s1 : s2;

    const int tid  = threadIdx.x;
    const int wid  = tid >> 5;
    const int lane = tid & 31;
    const int gr = lane >> 2;        // 0..7
    const int tg = lane & 3;         // 0..3
    const int wm = wid & 1;          // M half -> rows wm*32..+31
    const int wn = wid >> 1;         // N half -> cols wn*64..+63
    const int row0 = blockIdx.y * 64;
    const int col0 = colblk * 128;

    const int nChunks = Ktot >> 5;   // K-chunk 32

    // ---- async tile issue ----
    auto issue = [&](int st, int kc) {
        const int k0 = kc << 5;
#pragma unroll
        for (int it = 0; it < 4; it++) {          // A: 512 float4
            int i = tid + it * 128;
            int r = i >> 3;
            int c = (i & 7) << 2;
            int nb = (row0 + r < M) ? 16 : 0;
            cp16(aB[st] + (uint32_t)(r * 36 + c) * 4,
                 A + (size_t)(row0 + r) * Ktot + k0 + c, nb);
        }
#pragma unroll
        for (int it = 0; it < 8; it++) {          // W: 1024 float4
            int i = tid + it * 128;
            int r = i >> 3;
            int c = (i & 7) << 2;
            cp16(wB[st] + (uint32_t)(r * 36 + c) * 4,
                 W + (size_t)(col0 + r) * Ktot + k0 + c, 16);
        }
    };

    float acc[2][8][4];
#pragma unroll
    for (int mt = 0; mt < 2; mt++)
#pragma unroll
        for (int nt = 0; nt < 8; nt++)
#pragma unroll
            for (int j = 0; j < 4; j++) acc[mt][nt][j] = 0.f;

    issue(0, 0);
    asm volatile("cp.async.commit_group;" ::: "memory");

    for (int kc = 0; kc < nChunks; kc++) {
        const int st = kc & 1;
        if (kc + 1 < nChunks) issue(st ^ 1, kc + 1);
        asm volatile("cp.async.commit_group;" ::: "memory");
        asm volatile("cp.async.wait_group 1;" ::: "memory");
        __syncthreads();

        const float* As = Asm[st];
        const float* Ws = Wsm[st];
#pragma unroll
        for (int ks = 0; ks < 4; ks++) {
            const int k0s = ks * 8;
            uint32_t ta[2][4];
#pragma unroll
            for (int mf = 0; mf < 2; mf++) {
                int base = wm * 32 + mf * 16;
                ta[mf][0] = f2tf32(As[(base + gr)     * 36 + k0s + tg]);
                ta[mf][1] = f2tf32(As[(base + gr + 8) * 36 + k0s + tg]);
                ta[mf][2] = f2tf32(As[(base + gr)     * 36 + k0s + tg + 4]);
                ta[mf][3] = f2tf32(As[(base + gr + 8) * 36 + k0s + tg + 4]);
            }
#pragma unroll
            for (int nt = 0; nt < 8; nt++) {
                int n0 = wn * 64 + nt * 8;
                uint32_t tb[2];
                tb[0] = f2tf32(Ws[(n0 + gr) * 36 + k0s + tg]);
                tb[1] = f2tf32(Ws[(n0 + gr) * 36 + k0s + tg + 4]);
                mma_tf32(acc[0][nt], ta[0], tb);
                mma_tf32(acc[1][nt], ta[1], tb);
            }
        }
        __syncthreads();
    }

    // epilogue (m16n8 C layout: c0/c1 rows gr, c2/c3 rows gr+8; cols 2*tg, 2*tg+1)
    const int qc = tg * 2;
#pragma unroll
    for (int mt = 0; mt < 2; mt++) {
#pragma unroll
        for (int half = 0; half < 2; half++) {
            int r = row0 + wm * 32 + mt * 16 + gr + half * 8;
            if (r >= M) continue;
#pragma unroll
            for (int nt = 0; nt < 8; nt++) {
                int c = col0 + wn * 64 + nt * 8 + qc;
                float v0 = (acc[mt][nt][half * 2 + 0] + bias[c + 0]) * scale;
                float v1 = (acc[mt][nt][half * 2 + 1] + bias[c + 1]) * scale;
                if (doRelu) { v0 = fmaxf(v0, 0.f); v1 = fmaxf(v1, 0.f); }
                if (addend) {
                    float2 ad = *(const float2*)(addend + (size_t)r * Nn + c);
                    v0 += ad.x; v1 += ad.y;
                }
                *(float2*)(C + (size_t)r * Nn + c) = make_float2(v0, v1);
            }
        }
    }
}

// ---------------- fused edge attention: p=exp(q.k); den[src]+=p; xa[src]+=p*v[dst] ----------------
__global__ void attn_edge_kernel(const int* __restrict__ src, const int* __restrict__ dst) {
    int gid  = blockIdx.x * blockDim.x + threadIdx.x;
    int e    = gid >> 5;
    int lane = gid & 31;
    if (e >= NE) return;
    int sr = src[e], ds = dst[e];
    const float4 qv = *(const float4*)(g_q + (size_t)sr * HD + lane * 4);
    const float4 kv = *(const float4*)(g_k + (size_t)ds * HD + lane * 4);
    float part = qv.x * kv.x + qv.y * kv.y + qv.z * kv.z + qv.w * kv.w;
    part += __shfl_xor_sync(0xffffffffu, part, 1);
    part += __shfl_xor_sync(0xffffffffu, part, 2);   // per-head dot (4-lane group)
    float p = __expf(part);
    if ((lane & 3) == 0)
        atomicAdd(&g_den[sr * NHD + (lane >> 2)], p);
    float4 vv = *(const float4*)(g_v + (size_t)ds * HD + lane * 4);
    vv.x *= p; vv.y *= p; vv.z *= p; vv.w *= p;
    red4(&g_xa[(size_t)sr * HD + lane * 4], vv);
}

// ---------------- BN statistics (modes: plain / add / divide-by-den + add) ----------------
__global__ void stats_kernel(float* __restrict__ x, const float* __restrict__ add,
                             int slot, int divmode) {
    int c  = threadIdx.x;
    int r0 = blockIdx.x * 64;
    int hd = c >> 4;
    float s = 0.f, ss = 0.f;
    for (int i = 0; i < 64; i++) {
        int r = r0 + i;
        if (r < NND) {
            size_t idx = (size_t)r * HD + c;
            float v = x[idx];
            if (divmode) {
                float d = g_den[r * NHD + hd];
                v = (d > 0.f) ? (v / d) : 0.f;   // isolated node: empty segment -> 0
            }
            if (add) v += add[idx];
            if (add || divmode) x[idx] = v;
            s += v; ss += v * v;
        }
    }
    atomicAdd(&g_sum[slot * HD + c], s);
    atomicAdd(&g_ssq[slot * HD + c], ss);
}

// ---------------- hc = bn0(xl) + bn1(xa) ----------------
__global__ void combine_kernel(const float* __restrict__ nl_g, const float* __restrict__ nl_b,
                               const float* __restrict__ na_g, const float* __restrict__ na_b) {
    int i = blockIdx.x * blockDim.x + threadIdx.x;
    if (i >= NND * HD) return;
    int c = i & (HD - 1);
    const float invN = 1.f / (float)NND;
    float mu0 = g_sum[c] * invN;
    float v0  = g_ssq[c] * invN - mu0 * mu0;
    float i0  = rsqrtf(v0 + 1e-5f);
    float mu1 = g_sum[HD + c] * invN;
    float v1  = g_ssq[HD + c] * invN - mu1 * mu1;
    float i1  = rsqrtf(v1 + 1e-5f);
    float a = (g_xl[i] - mu0) * i0 * nl_g[c] + nl_b[c];
    float b = (g_xa[i] - mu1) * i1 * na_g[c] + na_b[c];
    g_hc[i] = a + b;
}

// ---------------- out = bn2(xo) ----------------
__global__ void apply_kernel(const float* __restrict__ no_g, const float* __restrict__ no_b,
                             float* __restrict__ out) {
    int i = blockIdx.x * blockDim.x + threadIdx.x;
    if (i >= NND * HD) return;
    int c = i & (HD - 1);
    const float invN = 1.f / (float)NND;
    float mu = g_sum[2 * HD + c] * invN;
    float v  = g_ssq[2 * HD + c] * invN - mu * mu;
    float iv = rsqrtf(v + 1e-5f);
    out[i] = (g_xo[i] - mu) * iv * no_g[c] + no_b[c];
}

// ---------------- host launcher ----------------
extern "C" void kernel_launch(void* const* d_in, const int* in_sizes, int n_in,
                              void* d_out, int out_size) {
    const float* h      = (const float*)d_in[0];
    const float* eattr  = (const float*)d_in[1];
    const int*   src    = (const int*)  d_in[2];
    const int*   dst    = (const int*)  d_in[3];
    const float* gin_w1 = (const float*)d_in[4];
    const float* gin_b1 = (const float*)d_in[5];
    const float* gin_w2 = (const float*)d_in[6];
    const float* gin_b2 = (const float*)d_in[7];
    const float* wq     = (const float*)d_in[8];
    const float* bq     = (const float*)d_in[9];
    const float* wk     = (const float*)d_in[10];
    const float* bk     = (const float*)d_in[11];
    const float* wv     = (const float*)d_in[12];
    const float* bv     = (const float*)d_in[13];
    const float* nl_g   = (const float*)d_in[14];
    const float* nl_b   = (const float*)d_in[15];
    const float* na_g   = (const float*)d_in[16];
    const float* na_b   = (const float*)d_in[17];
    const float* no_g   = (const float*)d_in[18];
    const float* no_b   = (const float*)d_in[19];
    const float* ffn1_w = (const float*)d_in[20];
    const float* ffn1_b = (const float*)d_in[21];
    const float* ffn2_w = (const float*)d_in[22];
    const float* ffn2_b = (const float*)d_in[23];
    float* out = (float*)d_out;

    float* p_agg; cudaGetSymbolAddress((void**)&p_agg, g_agg);
    float* p_t1;  cudaGetSymbolAddress((void**)&p_t1,  g_t1);
    float* p_xl;  cudaGetSymbolAddress((void**)&p_xl,  g_xl);
    float* p_q;   cudaGetSymbolAddress((void**)&p_q,   g_q);
    float* p_k;   cudaGetSymbolAddress((void**)&p_k,   g_k);
    float* p_v;   cudaGetSymbolAddress((void**)&p_v,   g_v);
    float* p_xa;  cudaGetSymbolAddress((void**)&p_xa,  g_xa);
    float* p_hc;  cudaGetSymbolAddress((void**)&p_hc,  g_hc);
    float* p_xo;  cudaGetSymbolAddress((void**)&p_xo,  g_xo);
    float* p_ffn; cudaGetSymbolAddress((void**)&p_ffn, g_ffn);

    cudaFuncSetAttribute(mma_gemm_kernel, cudaFuncAttributeMaxDynamicSharedMemorySize, GEMM_SMEM);

    const int M  = NND;
    const int MT = (M + 63) / 64;         // 782
    const float scale = 0.25f;            // DH^-0.5, DH=16

    zero_kernel<<<(NND * HD + 255) / 256, 256>>>(h);
    msg_kernel<<<(NE * 32 + 255) / 256, 256>>>(h, eattr, src, dst, out + (size_t)NND * HD);

    // gin MLP (g_agg already = h + sum(msg))
    mma_gemm_kernel<<<dim3(1, MT), 128, GEMM_SMEM>>>(
        p_agg, gin_w1, gin_w1, gin_w1, gin_b1, gin_b1, gin_b1,
        nullptr, p_t1, p_t1, p_t1, M, HD, HD, 1, 1.f, 1.f, 1.f);
    mma_gemm_kernel<<<dim3(1, MT), 128, GEMM_SMEM>>>(
        p_t1, gin_w2, gin_w2, gin_w2, gin_b2, gin_b2, gin_b2,
        h, p_xl, p_xl, p_xl, M, HD, HD, 0, 1.f, 1.f, 1.f);
    stats_kernel<<<(M + 63) / 64, 128>>>(p_xl, nullptr, 0, 0);

    // fused q/k/v projections (sel = blockIdx.x)
    mma_gemm_kernel<<<dim3(3, MT), 128, GEMM_SMEM>>>(
        h, wq, wk, wv, bq, bk, bv,
        nullptr, p_q, p_k, p_v, M, HD, HD, 0, scale, 1.f, 1.f);

    // fused sparse softmax attention (single edge pass, deferred normalization)
    attn_edge_kernel<<<(NE * 32 + 255) / 256, 256>>>(src, dst);
    stats_kernel<<<(M + 63) / 64, 128>>>(p_xa, h, 1, 1);   // xa = h + xa/den, + stats

    combine_kernel<<<(NND * HD + 255) / 256, 256>>>(nl_g, nl_b, na_g, na_b);

    // FFN + residual
    mma_gemm_kernel<<<dim3(2, MT), 128, GEMM_SMEM>>>(
        p_hc, ffn1_w, ffn1_w, ffn1_w, ffn1_b, ffn1_b, ffn1_b,
        nullptr, p_ffn, p_ffn, p_ffn, M, 2 * HD, HD, 1, 1.f, 1.f, 1.f);
    mma_gemm_kernel<<<dim3(1, MT), 128, GEMM_SMEM>>>(
        p_ffn, ffn2_w, ffn2_w, ffn2_w, ffn2_b, ffn2_b, ffn2_b,
        p_hc, p_xo, p_xo, p_xo, M, HD, 2 * HD, 0, 1.f, 1.f, 1.f);
    stats_kernel<<<(M + 63) / 64, 128>>>(p_xo, nullptr, 2, 0);

    apply_kernel<<<(NND * HD + 255) / 256, 256>>>(no_g, no_b, out);
}

// round 8
// speedup vs baseline: 1.8929x; 1.0881x over previous
#include <cuda_runtime.h>
#include <cuda_bf16.h>
#include <cstdint>
#include <cstddef>

#define NND 50000
#define NE  500000
#define HD  128
#define NHD 8

// ---------------- scratch (device globals: allocation-free) ----------------
__device__ float g_agg[NND * HD];
__device__ float g_t1 [NND * HD];
__device__ float g_xl [NND * HD];
__device__ float g_q  [NND * HD];
__device__ float g_k  [NND * HD];
__device__ float g_v  [NND * HD];
__device__ float g_xa [NND * HD];
__device__ float g_hc [NND * HD];
__device__ float g_xo [NND * HD];
__device__ float g_ffn[NND * 2 * HD];
__device__ float g_den[NND * NHD];
__device__ float g_sum[3 * HD];
__device__ float g_ssq[3 * HD];

// ---------------- helpers ----------------
__device__ __forceinline__ void red4(float* p, float4 v) {
    asm volatile("red.global.add.v4.f32 [%0], {%1,%2,%3,%4};"
                 :: "l"(p), "f"(v.x), "f"(v.y), "f"(v.z), "f"(v.w) : "memory");
}
__device__ __forceinline__ uint32_t smem_u32(const void* p) {
    uint32_t a;
    asm("{ .reg .u64 t; cvta.to.shared.u64 t, %1; cvt.u32.u64 %0, t; }" : "=r"(a) : "l"(p));
    return a;
}
__device__ __forceinline__ void cp16(uint32_t dst, const float* src, int nbytes) {
    asm volatile("cp.async.ca.shared.global [%0], [%1], 16, %2;"
                 :: "r"(dst), "l"(__cvta_generic_to_global(src)), "r"(nbytes) : "memory");
}
__device__ __forceinline__ uint32_t f2tf32(float f) {
    uint32_t r;
    asm("cvt.rna.tf32.f32 %0, %1;" : "=r"(r) : "f"(f));
    return r;
}
__device__ __forceinline__ void mma_tf32(float* c, const uint32_t* a, const uint32_t* b) {
    asm volatile("mma.sync.aligned.m16n8k8.row.col.f32.tf32.tf32.f32 "
                 "{%0,%1,%2,%3}, {%4,%5,%6,%7}, {%8,%9}, {%0,%1,%2,%3};"
                 : "+f"(c[0]), "+f"(c[1]), "+f"(c[2]), "+f"(c[3])
                 : "r"(a[0]), "r"(a[1]), "r"(a[2]), "r"(a[3]), "r"(b[0]), "r"(b[1]));
}

// ---------------- init scratch (g_agg = h : folds the GINE self-term) ----------------
__global__ void zero_kernel(const float* __restrict__ h) {
    int i = blockIdx.x * blockDim.x + threadIdx.x;
    if (i < NND * HD) { g_agg[i] = h[i]; g_xa[i] = 0.f; }
    if (i < NND * NHD) g_den[i] = 0.f;
    if (i < 3 * HD)   { g_sum[i] = 0.f; g_ssq[i] = 0.f; }
}

// ---------------- GINE message + eattr passthrough to output ----------------
__global__ void msg_kernel(const float* __restrict__ h, const float* __restrict__ eattr,
                           const int* __restrict__ src, const int* __restrict__ dst,
                           float* __restrict__ out_e) {
    int gid  = blockIdx.x * blockDim.x + threadIdx.x;
    int e    = gid >> 5;
    int lane = gid & 31;
    if (e >= NE) return;
    int sr = src[e], ds = dst[e];
    const float4 hv = *(const float4*)(h + (size_t)sr * HD + lane * 4);
    const float4 ev = *(const float4*)(eattr + (size_t)e * HD + lane * 4);
    *(float4*)(out_e + (size_t)e * HD + lane * 4) = ev;   // fused eattr copy-out
    float4 m;
    m.x = fmaxf(hv.x + ev.x, 0.f);
    m.y = fmaxf(hv.y + ev.y, 0.f);
    m.z = fmaxf(hv.z + ev.z, 0.f);
    m.w = fmaxf(hv.w + ev.w, 0.f);
    red4(&g_agg[(size_t)ds * HD + lane * 4], m);
}

// ---------------- tf32 mma.sync GEMM, cp.async 2-stage pipeline, fused BN stats ----------------
// C[M,Nn] = epi( A[M,Ktot] @ W[Nn,Ktot]^T + bias ) * scale ; relu? ; + addend?
// statSlot >= 0: accumulate per-column sum/sumsq of written C into g_sum/g_ssq[slot].
#define AS_F (64 * 36)
#define WS_F (128 * 36)
#define GEMM_SMEM ((2 * AS_F + 2 * WS_F) * 4)   // 55296 B
__global__ __launch_bounds__(128, 3)
void mma_gemm_kernel(const float* __restrict__ A,
                     const float* __restrict__ W0, const float* __restrict__ W1,
                     const float* __restrict__ W2,
                     const float* __restrict__ b0, const float* __restrict__ b1,
                     const float* __restrict__ b2,
                     const float* __restrict__ addend,
                     float* __restrict__ C0, float* __restrict__ C1, float* __restrict__ C2,
                     int M, int Nn, int Ktot, int doRelu,
                     float s0, float s1, float s2, int statSlot) {
    extern __shared__ float smf[];
    float* Asm[2] = { smf,          smf + AS_F };
    float* Wsm[2] = { smf + 2*AS_F, smf + 2*AS_F + WS_F };
    const uint32_t aB[2] = { smem_u32(Asm[0]), smem_u32(Asm[1]) };
    const uint32_t wB[2] = { smem_u32(Wsm[0]), smem_u32(Wsm[1]) };

    const int nColBlk = Nn >> 7;
    const int sel    = blockIdx.x / nColBlk;
    const int colblk = blockIdx.x - sel * nColBlk;
    const float* W    = (sel == 0) ? W0 : (sel == 1) ? W1 : W2;
    const float* bias = (sel == 0) ? b0 : (sel == 1) ? b1 : b2;
    float* C          = (sel == 0) ? C0 : (sel == 1) ? C1 : C2;
    const float scale = (sel == 0) ? s0 : (sel == 1) ? s1 : s2;

    const int tid  = threadIdx.x;
    const int wid  = tid >> 5;
    const int lane = tid & 31;
    const int gr = lane >> 2;
    const int tg = lane & 3;
    const int wm = wid & 1;
    const int wn = wid >> 1;
    const int row0 = blockIdx.y * 64;
    const int col0 = colblk * 128;

    const int nChunks = Ktot >> 5;

    auto issue = [&](int st, int kc) {
        const int k0 = kc << 5;
#pragma unroll
        for (int it = 0; it < 4; it++) {
            int i = tid + it * 128;
            int r = i >> 3;
            int c = (i & 7) << 2;
            int nb = (row0 + r < M) ? 16 : 0;
            cp16(aB[st] + (uint32_t)(r * 36 + c) * 4,
                 A + (size_t)(row0 + r) * Ktot + k0 + c, nb);
        }
#pragma unroll
        for (int it = 0; it < 8; it++) {
            int i = tid + it * 128;
            int r = i >> 3;
            int c = (i & 7) << 2;
            cp16(wB[st] + (uint32_t)(r * 36 + c) * 4,
                 W + (size_t)(col0 + r) * Ktot + k0 + c, 16);
        }
    };

    float acc[2][8][4];
#pragma unroll
    for (int mt = 0; mt < 2; mt++)
#pragma unroll
        for (int nt = 0; nt < 8; nt++)
#pragma unroll
            for (int j = 0; j < 4; j++) acc[mt][nt][j] = 0.f;

    issue(0, 0);
    asm volatile("cp.async.commit_group;" ::: "memory");

    for (int kc = 0; kc < nChunks; kc++) {
        const int st = kc & 1;
        if (kc + 1 < nChunks) issue(st ^ 1, kc + 1);
        asm volatile("cp.async.commit_group;" ::: "memory");
        asm volatile("cp.async.wait_group 1;" ::: "memory");
        __syncthreads();

        const float* As = Asm[st];
        const float* Ws = Wsm[st];
#pragma unroll
        for (int ks = 0; ks < 4; ks++) {
            const int k0s = ks * 8;
            uint32_t ta[2][4];
#pragma unroll
            for (int mf = 0; mf < 2; mf++) {
                int base = wm * 32 + mf * 16;
                ta[mf][0] = f2tf32(As[(base + gr)     * 36 + k0s + tg]);
                ta[mf][1] = f2tf32(As[(base + gr + 8) * 36 + k0s + tg]);
                ta[mf][2] = f2tf32(As[(base + gr)     * 36 + k0s + tg + 4]);
                ta[mf][3] = f2tf32(As[(base + gr + 8) * 36 + k0s + tg + 4]);
            }
#pragma unroll
            for (int nt = 0; nt < 8; nt++) {
                int n0 = wn * 64 + nt * 8;
                uint32_t tb[2];
                tb[0] = f2tf32(Ws[(n0 + gr) * 36 + k0s + tg]);
                tb[1] = f2tf32(Ws[(n0 + gr) * 36 + k0s + tg + 4]);
                mma_tf32(acc[0][nt], ta[0], tb);
                mma_tf32(acc[1][nt], ta[1], tb);
            }
        }
        __syncthreads();
    }

    // epilogue (+ optional fused BN stats)
    const int qc = tg * 2;
#pragma unroll
    for (int nt = 0; nt < 8; nt++) {
        int c = col0 + wn * 64 + nt * 8 + qc;
        float cs0 = 0.f, cs1 = 0.f, cq0 = 0.f, cq1 = 0.f;
#pragma unroll
        for (int mt = 0; mt < 2; mt++) {
#pragma unroll
            for (int half = 0; half < 2; half++) {
                int r = row0 + wm * 32 + mt * 16 + gr + half * 8;
                if (r >= M) continue;
                float v0 = (acc[mt][nt][half * 2 + 0] + bias[c + 0]) * scale;
                float v1 = (acc[mt][nt][half * 2 + 1] + bias[c + 1]) * scale;
                if (doRelu) { v0 = fmaxf(v0, 0.f); v1 = fmaxf(v1, 0.f); }
                if (addend) {
                    float2 ad = *(const float2*)(addend + (size_t)r * Nn + c);
                    v0 += ad.x; v1 += ad.y;
                }
                *(float2*)(C + (size_t)r * Nn + c) = make_float2(v0, v1);
                cs0 += v0; cs1 += v1;
                cq0 += v0 * v0; cq1 += v1 * v1;
            }
        }
        if (statSlot >= 0) {
#pragma unroll
            for (int m = 4; m <= 16; m <<= 1) {      // reduce over gr lanes
                cs0 += __shfl_xor_sync(0xffffffffu, cs0, m);
                cs1 += __shfl_xor_sync(0xffffffffu, cs1, m);
                cq0 += __shfl_xor_sync(0xffffffffu, cq0, m);
                cq1 += __shfl_xor_sync(0xffffffffu, cq1, m);
            }
            if (gr == 0) {
                int cc = c & (HD - 1);
                atomicAdd(&g_sum[statSlot * HD + cc + 0], cs0);
                atomicAdd(&g_sum[statSlot * HD + cc + 1], cs1);
                atomicAdd(&g_ssq[statSlot * HD + cc + 0], cq0);
                atomicAdd(&g_ssq[statSlot * HD + cc + 1], cq1);
            }
        }
    }
}

// ---------------- fused edge attention: p=exp(q.k); den[src]+=p; xa[src]+=p*v[dst] ----------------
__global__ void attn_edge_kernel(const int* __restrict__ src, const int* __restrict__ dst) {
    int gid  = blockIdx.x * blockDim.x + threadIdx.x;
    int e    = gid >> 5;
    int lane = gid & 31;
    if (e >= NE) return;
    int sr = src[e], ds = dst[e];
    const float4 qv = *(const float4*)(g_q + (size_t)sr * HD + lane * 4);
    const float4 kv = *(const float4*)(g_k + (size_t)ds * HD + lane * 4);
    float part = qv.x * kv.x + qv.y * kv.y + qv.z * kv.z + qv.w * kv.w;
    part += __shfl_xor_sync(0xffffffffu, part, 1);
    part += __shfl_xor_sync(0xffffffffu, part, 2);   // per-head dot (4-lane group)
    float p = __expf(part);
    if ((lane & 3) == 0)
        atomicAdd(&g_den[sr * NHD + (lane >> 2)], p);
    float4 vv = *(const float4*)(g_v + (size_t)ds * HD + lane * 4);
    vv.x *= p; vv.y *= p; vv.z *= p; vv.w *= p;
    red4(&g_xa[(size_t)sr * HD + lane * 4], vv);
}

// ---------------- BN statistics for xa (divide-by-den, add residual) ----------------
__global__ void stats_kernel(float* __restrict__ x, const float* __restrict__ add, int slot) {
    int c  = threadIdx.x;
    int r0 = blockIdx.x * 64;
    int hd = c >> 4;
    float s = 0.f, ss = 0.f;
    for (int i = 0; i < 64; i++) {
        int r = r0 + i;
        if (r < NND) {
            size_t idx = (size_t)r * HD + c;
            float v = x[idx];
            float d = g_den[r * NHD + hd];
            v = (d > 0.f) ? (v / d) : 0.f;   // isolated node: empty segment -> 0
            v += add[idx];
            x[idx] = v;
            s += v; ss += v * v;
        }
    }
    atomicAdd(&g_sum[slot * HD + c], s);
    atomicAdd(&g_ssq[slot * HD + c], ss);
}

// ---------------- hc = bn0(xl) + bn1(xa) ----------------
__global__ void combine_kernel(const float* __restrict__ nl_g, const float* __restrict__ nl_b,
                               const float* __restrict__ na_g, const float* __restrict__ na_b) {
    int i = blockIdx.x * blockDim.x + threadIdx.x;
    if (i >= NND * HD) return;
    int c = i & (HD - 1);
    const float invN = 1.f / (float)NND;
    float mu0 = g_sum[c] * invN;
    float v0  = g_ssq[c] * invN - mu0 * mu0;
    float i0  = rsqrtf(v0 + 1e-5f);
    float mu1 = g_sum[HD + c] * invN;
    float v1  = g_ssq[HD + c] * invN - mu1 * mu1;
    float i1  = rsqrtf(v1 + 1e-5f);
    float a = (g_xl[i] - mu0) * i0 * nl_g[c] + nl_b[c];
    float b = (g_xa[i] - mu1) * i1 * na_g[c] + na_b[c];
    g_hc[i] = a + b;
}

// ---------------- out = bn2(xo) ----------------
__global__ void apply_kernel(const float* __restrict__ no_g, const float* __restrict__ no_b,
                             float* __restrict__ out) {
    int i = blockIdx.x * blockDim.x + threadIdx.x;
    if (i >= NND * HD) return;
    int c = i & (HD - 1);
    const float invN = 1.f / (float)NND;
    float mu = g_sum[2 * HD + c] * invN;
    float v  = g_ssq[2 * HD + c] * invN - mu * mu;
    float iv = rsqrtf(v + 1e-5f);
    out[i] = (g_xo[i] - mu) * iv * no_g[c] + no_b[c];
}

// ---------------- host launcher ----------------
extern "C" void kernel_launch(void* const* d_in, const int* in_sizes, int n_in,
                              void* d_out, int out_size) {
    const float* h      = (const float*)d_in[0];
    const float* eattr  = (const float*)d_in[1];
    const int*   src    = (const int*)  d_in[2];
    const int*   dst    = (const int*)  d_in[3];
    const float* gin_w1 = (const float*)d_in[4];
    const float* gin_b1 = (const float*)d_in[5];
    const float* gin_w2 = (const float*)d_in[6];
    const float* gin_b2 = (const float*)d_in[7];
    const float* wq     = (const float*)d_in[8];
    const float* bq     = (const float*)d_in[9];
    const float* wk     = (const float*)d_in[10];
    const float* bk     = (const float*)d_in[11];
    const float* wv     = (const float*)d_in[12];
    const float* bv     = (const float*)d_in[13];
    const float* nl_g   = (const float*)d_in[14];
    const float* nl_b   = (const float*)d_in[15];
    const float* na_g   = (const float*)d_in[16];
    const float* na_b   = (const float*)d_in[17];
    const float* no_g   = (const float*)d_in[18];
    const float* no_b   = (const float*)d_in[19];
    const float* ffn1_w = (const float*)d_in[20];
    const float* ffn1_b = (const float*)d_in[21];
    const float* ffn2_w = (const float*)d_in[22];
    const float* ffn2_b = (const float*)d_in[23];
    float* out = (float*)d_out;

    float* p_agg; cudaGetSymbolAddress((void**)&p_agg, g_agg);
    float* p_t1;  cudaGetSymbolAddress((void**)&p_t1,  g_t1);
    float* p_xl;  cudaGetSymbolAddress((void**)&p_xl,  g_xl);
    float* p_q;   cudaGetSymbolAddress((void**)&p_q,   g_q);
    float* p_k;   cudaGetSymbolAddress((void**)&p_k,   g_k);
    float* p_v;   cudaGetSymbolAddress((void**)&p_v,   g_v);
    float* p_xa;  cudaGetSymbolAddress((void**)&p_xa,  g_xa);
    float* p_hc;  cudaGetSymbolAddress((void**)&p_hc,  g_hc);
    float* p_xo;  cudaGetSymbolAddress((void**)&p_xo,  g_xo);
    float* p_ffn; cudaGetSymbolAddress((void**)&p_ffn, g_ffn);

    static cudaStream_t s1 = nullptr;
    static cudaEvent_t evF = nullptr, evJ = nullptr;
    if (s1 == nullptr) {
        cudaStreamCreateWithFlags(&s1, cudaStreamNonBlocking);
        cudaEventCreateWithFlags(&evF, cudaEventDisableTiming);
        cudaEventCreateWithFlags(&evJ, cudaEventDisableTiming);
        cudaFuncSetAttribute(mma_gemm_kernel, cudaFuncAttributeMaxDynamicSharedMemorySize, GEMM_SMEM);
    }

    const int M  = NND;
    const int MT = (M + 63) / 64;         // 782
    const float scale = 0.25f;            // DH^-0.5, DH=16

    // ---- common init ----
    zero_kernel<<<(NND * HD + 255) / 256, 256>>>(h);
    cudaEventRecord(evF, 0);

    // ---- chain B (stream s1): qkv -> edge attention -> xa stats ----
    cudaStreamWaitEvent(s1, evF, 0);
    mma_gemm_kernel<<<dim3(3, MT), 128, GEMM_SMEM, s1>>>(
        h, wq, wk, wv, bq, bk, bv,
        nullptr, p_q, p_k, p_v, M, HD, HD, 0, scale, 1.f, 1.f, -1);
    attn_edge_kernel<<<(NE * 32 + 255) / 256, 256, 0, s1>>>(src, dst);
    stats_kernel<<<(M + 63) / 64, 128, 0, s1>>>(p_xa, h, 1);   // xa = h + xa/den, + stats
    cudaEventRecord(evJ, s1);

    // ---- chain A (capture stream): msg -> gin MLP (stats fused in gin2) ----
    msg_kernel<<<(NE * 32 + 255) / 256, 256>>>(h, eattr, src, dst, out + (size_t)NND * HD);
    mma_gemm_kernel<<<dim3(1, MT), 128, GEMM_SMEM>>>(
        p_agg, gin_w1, gin_w1, gin_w1, gin_b1, gin_b1, gin_b1,
        nullptr, p_t1, p_t1, p_t1, M, HD, HD, 1, 1.f, 1.f, 1.f, -1);
    mma_gemm_kernel<<<dim3(1, MT), 128, GEMM_SMEM>>>(
        p_t1, gin_w2, gin_w2, gin_w2, gin_b2, gin_b2, gin_b2,
        h, p_xl, p_xl, p_xl, M, HD, HD, 0, 1.f, 1.f, 1.f, 0);

    // ---- join ----
    cudaStreamWaitEvent(0, evJ, 0);
    combine_kernel<<<(NND * HD + 255) / 256, 256>>>(nl_g, nl_b, na_g, na_b);

    // ---- FFN + residual (stats fused in ffn2) ----
    mma_gemm_kernel<<<dim3(2, MT), 128, GEMM_SMEM>>>(
        p_hc, ffn1_w, ffn1_w, ffn1_w, ffn1_b, ffn1_b, ffn1_b,
        nullptr, p_ffn, p_ffn, p_ffn, M, 2 * HD, HD, 1, 1.f, 1.f, 1.f, -1);
    mma_gemm_kernel<<<dim3(1, MT), 128, GEMM_SMEM>>>(
        p_ffn, ffn2_w, ffn2_w, ffn2_w, ffn2_b, ffn2_b, ffn2_b,
        p_hc, p_xo, p_xo, p_xo, M, HD, 2 * HD, 0, 1.f, 1.f, 1.f, 2);

    apply_kernel<<<(NND * HD + 255) / 256, 256>>>(no_g, no_b, out);
}